// round 1
// baseline (speedup 1.0000x reference)
#include <cuda_runtime.h>
#include <math_constants.h>

#define BB 1024
#define VV 5000
#define NN 10000
#define TT 50
#define HH 200
#define KK 20

static __device__ __constant__ float c_ETA  = 0.5f;
static __device__ __constant__ float c_RHO  = 0.5f;
#define EPSV 1e-5f
#define CCV  0.25f
#define ALPHAV 1.0f

// ---------------- device scratch (no allocs allowed) ----------------
__device__ float g_e1[BB*HH];
__device__ float g_e2[BB*HH];
__device__ float g_lin3[BB*TT];
__device__ float g_part[4*BB*256];     // split-K partials, N padded to 256
__device__ float g_soft[BB*TT];
__device__ float g_snorm[BB];
__device__ int   g_enc[BB];
__device__ int   g_counts[TT];
__device__ float g_mean3[TT];
__device__ float g_rstd3[TT];
__device__ float g_zc[TT*VV];          // code logits
__device__ float g_zhat[TT*VV];        // BN'd code logits
__device__ float g_lse[TT];
__device__ float g_banknorm[NN];
__device__ float g_fuse[(size_t)BB*NN];// 41 MB
__device__ int   g_topk[BB*KK];
__device__ double g_acc[2];            // [0] rec sum, [1] e_latent sum

// ---------------- init ----------------
__global__ void k_init() {
    int t = threadIdx.x;
    if (t < TT) g_counts[t] = 0;
    if (t < 2)  g_acc[t] = 0.0;
}

// ---------------- generic NT GEMM (A[M,K] row-major, B[N,K] row-major) ----------------
// writes split-K partials into g_part[s][m][256]
__global__ void k_gemm_nt(const float* __restrict__ Aext, const float* __restrict__ Bm,
                          int M, int Nmat, int Kdim, int lda, int ldb, int aSel) {
    const float* A = Aext;
    if (aSel == 1) A = g_e1;
    else if (aSel == 2) A = g_e2;

    const int BM = 64, BN = 64, BK = 8;
    __shared__ float As[BK][BM + 4];
    __shared__ float Bs[BK][BN + 4];
    int bm = blockIdx.x * BM;
    int bn = blockIdx.y * BN;
    int s  = blockIdx.z;
    int splits = gridDim.z;
    int kchunk = (Kdim + splits - 1) / splits;
    int k0 = s * kchunk;
    int k1 = min(Kdim, k0 + kchunk);
    int tid = threadIdx.x;
    int tx = tid & 15, ty = tid >> 4;

    float acc[4][4];
#pragma unroll
    for (int i = 0; i < 4; i++)
#pragma unroll
        for (int j = 0; j < 4; j++) acc[i][j] = 0.f;

    for (int kt = k0; kt < k1; kt += BK) {
#pragma unroll
        for (int l = 0; l < 2; l++) {
            int e = tid + l * 256;
            int r = e >> 3, kk = e & 7;
            int gk = kt + kk;
            float va = 0.f, vb = 0.f;
            if (gk < k1 && (bm + r) < M)    va = A [(size_t)(bm + r) * lda + gk];
            if (gk < k1 && (bn + r) < Nmat) vb = Bm[(size_t)(bn + r) * ldb + gk];
            As[kk][r] = va;
            Bs[kk][r] = vb;
        }
        __syncthreads();
#pragma unroll
        for (int kk = 0; kk < BK; kk++) {
            float a[4], bv[4];
#pragma unroll
            for (int i = 0; i < 4; i++) a[i]  = As[kk][ty * 4 + i];
#pragma unroll
            for (int j = 0; j < 4; j++) bv[j] = Bs[kk][tx * 4 + j];
#pragma unroll
            for (int i = 0; i < 4; i++)
#pragma unroll
                for (int j = 0; j < 4; j++) acc[i][j] += a[i] * bv[j];
        }
        __syncthreads();
    }
    float* o = g_part + (size_t)s * BB * 256;
#pragma unroll
    for (int i = 0; i < 4; i++) {
        int m = bm + ty * 4 + i;
        if (m < M) {
#pragma unroll
            for (int j = 0; j < 4; j++) {
                int n = bn + tx * 4 + j;
                o[(size_t)m * 256 + n] = acc[i][j];
            }
        }
    }
}

// reduce split-K partials + bias + optional softplus. dstSel: 0->g_e1(H) 1->g_e2(H) 2->g_lin3(T)
__global__ void k_reduce_bias_act(int S, int Nreal, const float* __restrict__ bias,
                                  int act, int dstSel, int M) {
    int i = blockIdx.x * blockDim.x + threadIdx.x;
    int total = M * Nreal;
    if (i >= total) return;
    int m = i / Nreal, n = i - m * Nreal;
    float v = 0.f;
    for (int s = 0; s < S; s++) v += g_part[(size_t)s * BB * 256 + (size_t)m * 256 + n];
    v += bias[n];
    if (act == 1) v = (v > 0.f) ? v + log1pf(expf(-v)) : log1pf(expf(v));
    if (dstSel == 0)      g_e1  [(size_t)m * HH + n] = v;
    else if (dstSel == 1) g_e2  [(size_t)m * HH + n] = v;
    else                  g_lin3[(size_t)m * TT + n] = v;
}

// ---------------- theta BN stats (per column over batch) ----------------
__global__ void k_bn_stats_theta() {
    int t = blockIdx.x;
    __shared__ float ssum[256], ssq[256];
    float s = 0.f, q = 0.f;
    for (int m = threadIdx.x; m < BB; m += 256) {
        float v = g_lin3[m * TT + t];
        s += v; q += v * v;
    }
    ssum[threadIdx.x] = s; ssq[threadIdx.x] = q;
    __syncthreads();
    for (int o = 128; o > 0; o >>= 1) {
        if (threadIdx.x < o) { ssum[threadIdx.x] += ssum[threadIdx.x + o]; ssq[threadIdx.x] += ssq[threadIdx.x + o]; }
        __syncthreads();
    }
    if (threadIdx.x == 0) {
        float mean = ssum[0] / BB;
        float var  = ssq[0] / BB - mean * mean;
        g_mean3[t] = mean;
        g_rstd3[t] = rsqrtf(var + EPSV);
    }
}

// ---------------- BN apply + softmax + VQ argmin + e_latent + histogram ----------------
__global__ void k_vq(const float* __restrict__ gm, const float* __restrict__ bm,
                     const float* __restrict__ E) {
    int b = blockIdx.x;
    int t = threadIdx.x; // 64 threads
    __shared__ float sv[64];
    __shared__ int   si[64];
    __shared__ float s_s[TT];

    float th = -CUDART_INF_F;
    if (t < TT) th = (g_lin3[b * TT + t] - g_mean3[t]) * g_rstd3[t] * gm[t] + bm[t];

    sv[t] = th; __syncthreads();
    for (int o = 32; o > 0; o >>= 1) { if (t < o) sv[t] = fmaxf(sv[t], sv[t + o]); __syncthreads(); }
    float mx = sv[0]; __syncthreads();

    float ex = (t < TT) ? expf(th - mx) : 0.f;
    sv[t] = ex; __syncthreads();
    for (int o = 32; o > 0; o >>= 1) { if (t < o) sv[t] += sv[t + o]; __syncthreads(); }
    float sum = sv[0]; __syncthreads();

    float sval = ex / sum;
    if (t < TT) { s_s[t] = sval; g_soft[b * TT + t] = sval; }

    sv[t] = (t < TT) ? sval * sval : 0.f; __syncthreads();
    for (int o = 32; o > 0; o >>= 1) { if (t < o) sv[t] += sv[t + o]; __syncthreads(); }
    if (t == 0) g_snorm[b] = sv[0];
    __syncthreads();

    // distances d_j = ||E_j||^2 - 2 s.E_j  (||s||^2 constant per row)
    float dj = CUDART_INF_F;
    if (t < TT) {
        float dot = 0.f, en = 0.f;
        for (int u = 0; u < TT; u++) {
            float e = E[t * TT + u];
            dot += e * s_s[u];
            en  += e * e;
        }
        dj = en - 2.f * dot;
    }
    sv[t] = dj; si[t] = t; __syncthreads();
    for (int o = 32; o > 0; o >>= 1) {
        if (t < o) {
            if (sv[t + o] < sv[t] || (sv[t + o] == sv[t] && si[t + o] < si[t])) {
                sv[t] = sv[t + o]; si[t] = si[t + o];
            }
        }
        __syncthreads();
    }
    int jmin = si[0];
    __syncthreads();
    if (t == 0) { g_enc[b] = jmin; atomicAdd(&g_counts[jmin], 1); }

    float diff = (t < TT) ? (E[jmin * TT + t] - sval) : 0.f;
    sv[t] = diff * diff; __syncthreads();
    for (int o = 32; o > 0; o >>= 1) { if (t < o) sv[t] += sv[t + o]; __syncthreads(); }
    if (t == 0) atomicAdd(&g_acc[1], (double)sv[0]);
}

// ---------------- code logits zc[c][v] = sum_t E[c][t]*Wd[v][t] ----------------
__global__ void k_zc(const float* __restrict__ Wd, const float* __restrict__ E) {
    __shared__ float Es[TT * TT];
    for (int i = threadIdx.x; i < TT * TT; i += 256) Es[i] = E[i];
    __syncthreads();
    int v = blockIdx.x * 256 + threadIdx.x;
    if (v >= VV) return;
    float w[TT];
#pragma unroll
    for (int t = 0; t < TT; t++) w[t] = Wd[(size_t)v * TT + t];
    for (int c = 0; c < TT; c++) {
        float a = 0.f;
#pragma unroll
        for (int t = 0; t < TT; t++) a += Es[c * TT + t] * w[t];
        g_zc[(size_t)c * VV + v] = a;
    }
}

// ---------------- decoder BN via code histogram ----------------
__global__ void k_decbn(const float* __restrict__ gd, const float* __restrict__ bd) {
    __shared__ float cnt[TT];
    for (int i = threadIdx.x; i < TT; i += 256) cnt[i] = (float)g_counts[i];
    __syncthreads();
    int v = blockIdx.x * 256 + threadIdx.x;
    if (v >= VV) return;
    float m = 0.f, q = 0.f;
    for (int c = 0; c < TT; c++) {
        float z = g_zc[(size_t)c * VV + v];
        m += cnt[c] * z; q += cnt[c] * z * z;
    }
    m /= BB; q /= BB;
    float rstd = rsqrtf(q - m * m + EPSV);
    float gg = gd[v], bbv = bd[v];
    for (int c = 0; c < TT; c++) {
        g_zhat[(size_t)c * VV + v] = (g_zc[(size_t)c * VV + v] - m) * rstd * gg + bbv;
    }
}

// ---------------- per-code logsumexp ----------------
__global__ void k_lse() {
    int c = blockIdx.x;
    __shared__ float sm[256];
    const float* z = g_zhat + (size_t)c * VV;
    float mx = -CUDART_INF_F;
    for (int v = threadIdx.x; v < VV; v += 256) mx = fmaxf(mx, z[v]);
    sm[threadIdx.x] = mx; __syncthreads();
    for (int o = 128; o > 0; o >>= 1) { if (threadIdx.x < o) sm[threadIdx.x] = fmaxf(sm[threadIdx.x], sm[threadIdx.x + o]); __syncthreads(); }
    mx = sm[0]; __syncthreads();
    float s = 0.f;
    for (int v = threadIdx.x; v < VV; v += 256) s += expf(z[v] - mx);
    sm[threadIdx.x] = s; __syncthreads();
    for (int o = 128; o > 0; o >>= 1) { if (threadIdx.x < o) sm[threadIdx.x] += sm[threadIdx.x + o]; __syncthreads(); }
    if (threadIdx.x == 0) g_lse[c] = mx + logf(sm[0]);
}

// ---------------- bank norms ----------------
__global__ void k_banknorm(const float* __restrict__ bank) {
    int n = blockIdx.x * 256 + threadIdx.x;
    if (n < NN) {
        float s = 0.f;
        const float* r = bank + (size_t)n * TT;
#pragma unroll
        for (int t = 0; t < TT; t++) { float v = r[t]; s += v * v; }
        g_banknorm[n] = s;
    }
}

// ---------------- distance GEMM + fuse epilogue ----------------
__global__ void k_fuse(const float* __restrict__ bank, const float* __restrict__ Mcos,
                       const float* __restrict__ Mcoo, const int* __restrict__ idx) {
    __shared__ float As[TT][64 + 2];
    __shared__ float Bs[TT][64 + 2];
    int bm = blockIdx.x * 64, bn = blockIdx.y * 64;
    int tid = threadIdx.x;
    for (int e = tid; e < 64 * TT; e += 256) {
        int r = e / TT, kk = e - r * TT;
        As[kk][r] = g_soft[(size_t)(bm + r) * TT + kk];
        int nn = bn + r;
        Bs[kk][r] = (nn < NN) ? bank[(size_t)nn * TT + kk] : 0.f;
    }
    __syncthreads();
    int tx = tid & 15, ty = tid >> 4;
    float acc[4][4];
#pragma unroll
    for (int i = 0; i < 4; i++)
#pragma unroll
        for (int j = 0; j < 4; j++) acc[i][j] = 0.f;
    for (int kk = 0; kk < TT; kk++) {
        float a[4], bv[4];
#pragma unroll
        for (int i = 0; i < 4; i++) a[i]  = As[kk][ty * 4 + i];
#pragma unroll
        for (int j = 0; j < 4; j++) bv[j] = Bs[kk][tx * 4 + j];
#pragma unroll
        for (int i = 0; i < 4; i++)
#pragma unroll
            for (int j = 0; j < 4; j++) acc[i][j] += a[i] * bv[j];
    }
#pragma unroll
    for (int i = 0; i < 4; i++) {
        int m = bm + ty * 4 + i;
        int ib = idx[m];
        float sn = g_snorm[m];
        size_t cbase = (size_t)ib * NN;
#pragma unroll
        for (int j = 0; j < 4; j++) {
            int n = bn + tx * 4 + j;
            if (n < NN) {
                float cost = sn + g_banknorm[n] - 2.f * acc[i][j];
                float tdd  = cost * cost;
                float bow  = c_RHO * Mcos[cbase + n] + (1.f - c_RHO) * Mcoo[cbase + n];
                float f    = c_ETA * tdd + (1.f - c_ETA) * bow;
                if (n == ib) f = CUDART_INF_F;
                g_fuse[(size_t)m * NN + n] = f;
            }
        }
    }
}

// ---------------- top-K smallest per row ----------------
__global__ void k_topk() {
    int b = blockIdx.x;
    const float* row = g_fuse + (size_t)b * NN;
    float val[KK]; int ind[KK];
#pragma unroll
    for (int i = 0; i < KK; i++) { val[i] = CUDART_INF_F; ind[i] = 0x7fffffff; }
    for (int n = threadIdx.x; n < NN; n += 256) {
        float f = row[n];
        if (f < val[KK - 1] || (f == val[KK - 1] && n < ind[KK - 1])) {
            int p = KK - 1;
            while (p > 0 && (f < val[p - 1] || (f == val[p - 1] && n < ind[p - 1]))) {
                val[p] = val[p - 1]; ind[p] = ind[p - 1]; p--;
            }
            val[p] = f; ind[p] = n;
        }
    }
    __shared__ float sv[256 * KK];
    __shared__ int   sidx[256 * KK];
    __shared__ float rv[256];
    __shared__ int   ri[256];
    __shared__ int   rp[256];
#pragma unroll
    for (int i = 0; i < KK; i++) { sv[threadIdx.x * KK + i] = val[i]; sidx[threadIdx.x * KK + i] = ind[i]; }
    __syncthreads();
    for (int sel = 0; sel < KK; sel++) {
        float bvv = CUDART_INF_F; int bi = 0x7fffffff; int bp = threadIdx.x * KK;
        for (int i = 0; i < KK; i++) {
            float v = sv[threadIdx.x * KK + i]; int id = sidx[threadIdx.x * KK + i];
            if (v < bvv || (v == bvv && id < bi)) { bvv = v; bi = id; bp = threadIdx.x * KK + i; }
        }
        rv[threadIdx.x] = bvv; ri[threadIdx.x] = bi; rp[threadIdx.x] = bp;
        __syncthreads();
        for (int o = 128; o > 0; o >>= 1) {
            if (threadIdx.x < o) {
                if (rv[threadIdx.x + o] < rv[threadIdx.x] ||
                    (rv[threadIdx.x + o] == rv[threadIdx.x] && ri[threadIdx.x + o] < ri[threadIdx.x])) {
                    rv[threadIdx.x] = rv[threadIdx.x + o];
                    ri[threadIdx.x] = ri[threadIdx.x + o];
                    rp[threadIdx.x] = rp[threadIdx.x + o];
                }
            }
            __syncthreads();
        }
        if (threadIdx.x == 0) {
            g_topk[b * KK + sel] = ri[0];
            sv[rp[0]] = CUDART_INF_F;
        }
        __syncthreads();
    }
}

// ---------------- reconstruction loss (gather + dot decomposition) ----------------
__global__ void k_rec(const float* __restrict__ inputs, const float* __restrict__ training,
                      const int* __restrict__ is_aug) {
    int b = blockIdx.x;
    int e = g_enc[b];
    const float* z  = g_zhat + (size_t)e * VV;
    const float* xr = inputs + (size_t)b * VV;
    float dotI = 0.f, sumI = 0.f;
    for (int v = threadIdx.x; v < VV; v += 256) {
        float x = xr[v];
        dotI += x * z[v];
        sumI += x;
    }
    float dotA = 0.f, sumA = 0.f;
    if (is_aug[0] != 0) {
        for (int k = 0; k < KK; k++) {
            const float* tr = training + (size_t)g_topk[b * KK + k] * VV;
            for (int v = threadIdx.x; v < VV; v += 256) {
                float x = tr[v];
                dotA += x * z[v];
                sumA += x;
            }
        }
    }
    __shared__ float r1[256], r2[256], r3[256], r4[256];
    r1[threadIdx.x] = dotI; r2[threadIdx.x] = sumI; r3[threadIdx.x] = dotA; r4[threadIdx.x] = sumA;
    __syncthreads();
    for (int o = 128; o > 0; o >>= 1) {
        if (threadIdx.x < o) {
            r1[threadIdx.x] += r1[threadIdx.x + o];
            r2[threadIdx.x] += r2[threadIdx.x + o];
            r3[threadIdx.x] += r3[threadIdx.x + o];
            r4[threadIdx.x] += r4[threadIdx.x + o];
        }
        __syncthreads();
    }
    if (threadIdx.x == 0) {
        float scale = ALPHAV / (float)KK;
        double td = (double)r1[0] + (double)scale * r3[0];
        double ts = (double)r2[0] + (double)scale * r4[0];
        double contrib = (double)g_lse[e] * ts - td;
        atomicAdd(&g_acc[0], contrib);
    }
}

// ---------------- final ----------------
__global__ void k_final(float* out) {
    if (threadIdx.x == 0) {
        double rec = g_acc[0] / (double)BB;
        double ql  = (1.0 + (double)CCV) * (g_acc[1] / (double)(BB * TT));
        out[0] = (float)(rec + ql);
    }
}

// ---------------- launch ----------------
extern "C" void kernel_launch(void* const* d_in, const int* in_sizes, int n_in,
                              void* d_out, int out_size) {
    const int*   idx      = (const int*)  d_in[0];
    const float* inputs   = (const float*)d_in[1];
    const int*   is_aug   = (const int*)  d_in[2];
    const float* training = (const float*)d_in[3];
    const float* Mcos     = (const float*)d_in[4];
    const float* Mcoo     = (const float*)d_in[5];
    const float* bank     = (const float*)d_in[6];
    const float* W11      = (const float*)d_in[7];
    const float* b11      = (const float*)d_in[8];
    const float* W12      = (const float*)d_in[9];
    const float* b12      = (const float*)d_in[10];
    const float* W21      = (const float*)d_in[11];
    const float* b21      = (const float*)d_in[12];
    const float* gm       = (const float*)d_in[13];
    const float* bm       = (const float*)d_in[14];
    const float* gd       = (const float*)d_in[15];
    const float* bd       = (const float*)d_in[16];
    const float* Wd       = (const float*)d_in[17];
    const float* E        = (const float*)d_in[18];
    float* out = (float*)d_out;

    k_init<<<1, 64>>>();

    // encoder layer 1: softplus(inputs @ W11^T + b11), split-K=4
    k_gemm_nt<<<dim3(16, 4, 4), 256>>>(inputs, W11, BB, HH, VV, VV, VV, 0);
    k_reduce_bias_act<<<(BB * HH + 255) / 256, 256>>>(4, HH, b11, 1, 0, BB);

    // encoder layer 2: softplus(e1 @ W12^T + b12)
    k_gemm_nt<<<dim3(16, 4, 1), 256>>>(nullptr, W12, BB, HH, HH, HH, HH, 1);
    k_reduce_bias_act<<<(BB * HH + 255) / 256, 256>>>(1, HH, b12, 1, 1, BB);

    // theta linear: e2 @ W21^T + b21
    k_gemm_nt<<<dim3(16, 1, 1), 256>>>(nullptr, W21, BB, TT, HH, HH, HH, 2);
    k_reduce_bias_act<<<(BB * TT + 255) / 256, 256>>>(1, TT, b21, 0, 2, BB);

    // BN stats + BN/softmax/VQ
    k_bn_stats_theta<<<TT, 256>>>();
    k_vq<<<BB, 64>>>(gm, bm, E);

    // decoder per-code pipeline
    k_zc<<<(VV + 255) / 256, 256>>>(Wd, E);
    k_decbn<<<(VV + 255) / 256, 256>>>(gd, bd);
    k_lse<<<TT, 256>>>();

    // augmentation: distances, fuse, topk
    k_banknorm<<<(NN + 255) / 256, 256>>>(bank);
    k_fuse<<<dim3(16, (NN + 63) / 64), 256>>>(bank, Mcos, Mcoo, idx);
    k_topk<<<BB, 256>>>();

    // reconstruction loss + final
    k_rec<<<BB, 256>>>(inputs, training, is_aug);
    k_final<<<1, 1>>>(out);
}